// round 1
// baseline (speedup 1.0000x reference)
#include <cuda_runtime.h>
#include <cstdint>

// Unfold (im2col): x[B=32, C=64, H=64, W=64] f32, K=3x3, stride=1
//   -> out[B=32, C*9=576, L=62*62=3844] f32
// out[b][c*9 + ki*3 + kj][i*62 + j] = x[b][c][i+ki][j+kj]
//
// One thread produces one float4 of one output row (row = (b*64+c)*9 + k).
// Output rows are 3844 floats (16B-multiple) so every row is float4-aligned.
// Loads are scalar (wrap across i-boundaries), but input is L2-resident
// (33.5 MB < 126 MB L2) so this kernel is DRAM-write-bound.

#define HW     64            // input H == W
#define WO     62            // output spatial dim
#define L      (WO * WO)     // 3844
#define NVEC   (L / 4)       // 961 float4 per output row

__global__ __launch_bounds__(256)
void unfold_kernel(const float* __restrict__ x, float* __restrict__ out)
{
    const int m = blockIdx.x * blockDim.x + threadIdx.x;  // float4 index in row
    if (m >= NVEC) return;
    const int r = blockIdx.y;                             // output row id

    const int k  = r % 9;
    const int bc = r / 9;                                 // b*64 + c
    const int ki = k / 3;
    const int kj = k - ki * 3;

    const float* __restrict__ src =
        x + (size_t)bc * (HW * HW) + (size_t)ki * HW + kj;

    const int l = m * 4;
    int i = l / WO;            // constant divisor -> mul-high
    int j = l - i * WO;

    float4 v;
    float* vp = reinterpret_cast<float*>(&v);
#pragma unroll
    for (int e = 0; e < 4; ++e) {
        vp[e] = src[i * HW + j];
        ++j;
        if (j == WO) { j = 0; ++i; }
    }

    reinterpret_cast<float4*>(out)[(size_t)r * NVEC + m] = v;
}

extern "C" void kernel_launch(void* const* d_in, const int* in_sizes, int n_in,
                              void* d_out, int out_size)
{
    const float* x = (const float*)d_in[0];
    float* out = (float*)d_out;

    // rows = B * C * 9 = 32 * 64 * 9 = 18432 ; NVEC=961 -> grid.x = 4 @ 256 thr
    dim3 block(256, 1, 1);
    dim3 grid((NVEC + 255) / 256, 18432, 1);
    unfold_kernel<<<grid, block>>>(x, out);
}

// round 2
// speedup vs baseline: 1.1641x; 1.1641x over previous
#include <cuda_runtime.h>
#include <cstdint>

// Unfold (im2col): x[B=32, C=64, H=64, W=64] f32, K=3x3, stride=1
//   -> out[B=32, C*9=576, L=62*62=3844] f32
//
// Elementwise mapping, one block per output row r = (b*64+c)*9 + k.
// For row r: out[r][l] = x[bc*4096 + ki*64 + kj + i*64 + j]   (l = i*62 + j)
//                      = src[l + 2*i]  where src = x + bc*4096 + ki*64 + kj
// so each element needs only i = l/62 (const-divide) + 2 adds.
// Lanes take consecutive l -> loads and stores are each a single fully
// coalesced 128B wavefront per warp instruction (vs ~20 wf/512B before).

#define HW   64
#define WO   62
#define L    (WO * WO)        // 3844
#define ROWS (32 * 64 * 9)    // 18432

__global__ __launch_bounds__(256)
void unfold_kernel(const float* __restrict__ x, float* __restrict__ out)
{
    const int r  = blockIdx.x;            // output row id
    const int k  = r % 9;
    const int bc = r / 9;
    const int ki = k / 3;
    const int kj = k - ki * 3;

    const float* __restrict__ src = x + (size_t)bc * (HW * HW) + ki * HW + kj;
    float* __restrict__ dst       = out + (size_t)r * L;

    unsigned l = threadIdx.x;

    // 3844 = 15*256 + 4
#pragma unroll 5
    for (int it = 0; it < 15; ++it, l += 256) {
        unsigned i = l / WO;              // mulhi with constant 62
        dst[l] = src[l + 2u * i];
    }
    if (l < L) {                          // tail: only tid < 4
        unsigned i = l / WO;
        dst[l] = src[l + 2u * i];
    }
}

extern "C" void kernel_launch(void* const* d_in, const int* in_sizes, int n_in,
                              void* d_out, int out_size)
{
    const float* x = (const float*)d_in[0];
    float* out = (float*)d_out;

    unfold_kernel<<<ROWS, 256>>>(x, out);
}